// round 1
// baseline (speedup 1.0000x reference)
#include <cuda_runtime.h>
#include <cuda_fp16.h>

#define NN 8192
#define EPSI 0.1f
#define NITERS 50
#define CHUNK 911          // ceil(8192/9) rows per col-structured block
#define ROWBLOCKS 148

// K = exp(M/eps) in fp16, row-major. 128MB static device scratch.
__device__ __half dK[(size_t)NN * NN];
__device__ float dU[NN];                         // u = a/(K v)
__device__ float dColAcc[(NITERS + 1) * NN];     // colAcc[k] -> v_k = b/colAcc[k]
__device__ float dR[NN];                         // row sums of target
__device__ float dCs[NN];                        // col sums of target
__device__ float dDot;                           // sum(target * M)

__global__ void init_kernel(const float* __restrict__ b) {
    int i = blockIdx.x * blockDim.x + threadIdx.x;
    if (i < NN) {
        dR[i] = 0.f;
        dCs[i] = 0.f;
        dColAcc[i] = b[i];                       // v_0 = b / b = 1
        for (int k = 1; k <= NITERS; k++) dColAcc[(size_t)k * NN + i] = 0.f;
    }
    if (i == 0) dDot = 0.f;
}

// One pass over M and target: build K (fp16), row/col sums of target, dot(target, M).
// Grid (32 col-tiles of 256, 9 row-chunks of 911), 256 threads.
__global__ void prep_kernel(const float* __restrict__ M, const float* __restrict__ T) {
    __shared__ float sred[8 * 256];
    __shared__ float sdot[256];
    const int w = threadIdx.x >> 5, l = threadIdx.x & 31;
    const int col0 = blockIdx.x * 256 + l * 8;
    const int r0 = blockIdx.y * CHUNK;
    const int rend = min(NN, r0 + CHUNK);
    const float SC = 10.0f * 1.4426950408889634f;   // (1/eps) * log2(e)

    float cs[8];
#pragma unroll
    for (int k = 0; k < 8; k++) cs[k] = 0.f;
    float dot = 0.f;

    for (int r = r0 + w; r < rend; r += 8) {
        size_t base = (size_t)r * NN + col0;
        float4 m0 = *reinterpret_cast<const float4*>(M + base);
        float4 m1 = *reinterpret_cast<const float4*>(M + base + 4);
        float4 t0 = *reinterpret_cast<const float4*>(T + base);
        float4 t1 = *reinterpret_cast<const float4*>(T + base + 4);

        union { uint4 u; __half2 h[4]; } P;
        P.h[0] = __floats2half2_rn(exp2f(m0.x * SC), exp2f(m0.y * SC));
        P.h[1] = __floats2half2_rn(exp2f(m0.z * SC), exp2f(m0.w * SC));
        P.h[2] = __floats2half2_rn(exp2f(m1.x * SC), exp2f(m1.y * SC));
        P.h[3] = __floats2half2_rn(exp2f(m1.z * SC), exp2f(m1.w * SC));
        *reinterpret_cast<uint4*>(dK + base) = P.u;

        cs[0] += t0.x; cs[1] += t0.y; cs[2] += t0.z; cs[3] += t0.w;
        cs[4] += t1.x; cs[5] += t1.y; cs[6] += t1.z; cs[7] += t1.w;

        dot += m0.x * t0.x + m0.y * t0.y + m0.z * t0.z + m0.w * t0.w
             + m1.x * t1.x + m1.y * t1.y + m1.z * t1.z + m1.w * t1.w;

        float rs = t0.x + t0.y + t0.z + t0.w + t1.x + t1.y + t1.z + t1.w;
#pragma unroll
        for (int o = 16; o > 0; o >>= 1) rs += __shfl_xor_sync(0xffffffffu, rs, o);
        if (l == 0) atomicAdd(&dR[r], rs);
    }

#pragma unroll
    for (int k = 0; k < 8; k++) sred[w * 256 + l * 8 + k] = cs[k];
    sdot[threadIdx.x] = dot;
    __syncthreads();

    float s = 0.f;
#pragma unroll
    for (int w2 = 0; w2 < 8; w2++) s += sred[w2 * 256 + threadIdx.x];
    atomicAdd(&dCs[blockIdx.x * 256 + threadIdx.x], s);

    for (int off = 128; off > 0; off >>= 1) {
        if (threadIdx.x < off) sdot[threadIdx.x] += sdot[threadIdx.x + off];
        __syncthreads();
    }
    if (threadIdx.x == 0) atomicAdd(&dDot, sdot[0]);
}

// u_i = a_i / sum_j K_ij * v_j, with v_j = b_j / colAcc[iter][j] built in smem.
// Grid 148 blocks x 512 threads; each warp owns whole rows.
__global__ void __launch_bounds__(512) row_gemv(const float* __restrict__ a,
                                                const float* __restrict__ b, int iter) {
    __shared__ float sv[NN];                    // 32KB: v vector
    const float* acc = dColAcc + (size_t)iter * NN;
    for (int j = threadIdx.x; j < NN; j += 512) sv[j] = b[j] / acc[j];
    __syncthreads();

    const int w = threadIdx.x >> 5, l = threadIdx.x & 31;
    const float4* sv4 = reinterpret_cast<const float4*>(sv);
    const int nm = (NN - blockIdx.x + (ROWBLOCKS - 1)) / ROWBLOCKS;

    for (int m = w; m < nm; m += 16) {
        const int r = blockIdx.x + m * ROWBLOCKS;
        const uint4* Kr = reinterpret_cast<const uint4*>(dK + (size_t)r * NN);
        float sum = 0.f;
#pragma unroll 4
        for (int v = l; v < NN / 8; v += 32) {
            union { uint4 u; __half2 h[4]; } U;
            U.u = Kr[v];
            float4 a0 = sv4[2 * v];
            float4 a1 = sv4[2 * v + 1];
            float2 f0 = __half22float2(U.h[0]);
            float2 f1 = __half22float2(U.h[1]);
            float2 f2 = __half22float2(U.h[2]);
            float2 f3 = __half22float2(U.h[3]);
            sum += f0.x * a0.x + f0.y * a0.y + f1.x * a0.z + f1.y * a0.w
                 + f2.x * a1.x + f2.y * a1.y + f3.x * a1.z + f3.y * a1.w;
        }
#pragma unroll
        for (int o = 16; o > 0; o >>= 1) sum += __shfl_xor_sync(0xffffffffu, sum, o);
        if (l == 0) dU[r] = a[r] / sum;
    }
}

// colAcc[iter+1][j] = sum_i K_ij * u_i. Grid (32 col-tiles, 9 row-chunks), 256 threads.
// Each lane owns 8 fixed columns -> register accumulation, then smem+atomic combine.
__global__ void col_gemv(int iter) {
    __shared__ float su[CHUNK];
    __shared__ float sred[8 * 256];
    const int r0 = blockIdx.y * CHUNK;
    const int rend = min(NN, r0 + CHUNK);
    for (int i = threadIdx.x; i < rend - r0; i += 256) su[i] = dU[r0 + i];
    __syncthreads();

    const int w = threadIdx.x >> 5, l = threadIdx.x & 31;
    const int col0 = blockIdx.x * 256 + l * 8;
    float acc[8];
#pragma unroll
    for (int k = 0; k < 8; k++) acc[k] = 0.f;

#pragma unroll 2
    for (int r = r0 + w; r < rend; r += 8) {
        union { uint4 u; __half2 h[4]; } U;
        U.u = *reinterpret_cast<const uint4*>(dK + (size_t)r * NN + col0);
        float uu = su[r - r0];
        float2 f0 = __half22float2(U.h[0]);
        float2 f1 = __half22float2(U.h[1]);
        float2 f2 = __half22float2(U.h[2]);
        float2 f3 = __half22float2(U.h[3]);
        acc[0] += f0.x * uu; acc[1] += f0.y * uu;
        acc[2] += f1.x * uu; acc[3] += f1.y * uu;
        acc[4] += f2.x * uu; acc[5] += f2.y * uu;
        acc[6] += f3.x * uu; acc[7] += f3.y * uu;
    }

#pragma unroll
    for (int k = 0; k < 8; k++) sred[w * 256 + l * 8 + k] = acc[k];
    __syncthreads();
    float s = 0.f;
#pragma unroll
    for (int w2 = 0; w2 < 8; w2++) s += sred[w2 * 256 + threadIdx.x];
    atomicAdd(&dColAcc[(size_t)(iter + 1) * NN + blockIdx.x * 256 + threadIdx.x], s);
}

// loss = -( dot(target,M)/eps + sum_i R_i*ln(u_i) + sum_j C_j*ln(v_j) )
__global__ void loss_kernel(const float* __restrict__ a, const float* __restrict__ b,
                            float* __restrict__ out) {
    __shared__ float sred[1024];
    const float* accL = dColAcc + (size_t)NITERS * NN;
    float p = 0.f;
    for (int i = threadIdx.x; i < NN; i += 1024) {
        p += dR[i] * logf(dU[i]);
        p += dCs[i] * (logf(b[i]) - logf(accL[i]));
    }
    sred[threadIdx.x] = p;
    __syncthreads();
    for (int off = 512; off > 0; off >>= 1) {
        if (threadIdx.x < off) sred[threadIdx.x] += sred[threadIdx.x + off];
        __syncthreads();
    }
    if (threadIdx.x == 0) out[0] = -(sred[0] + dDot * (1.0f / EPSI));
}

extern "C" void kernel_launch(void* const* d_in, const int* in_sizes, int n_in,
                              void* d_out, int out_size) {
    const float* M = (const float*)d_in[0];
    const float* T = (const float*)d_in[1];
    const float* a = (const float*)d_in[2];
    const float* b = (const float*)d_in[3];
    float* out = (float*)d_out;

    init_kernel<<<(NN + 255) / 256, 256>>>(b);
    prep_kernel<<<dim3(32, 9), 256>>>(M, T);
    for (int k = 0; k < NITERS; k++) {
        row_gemv<<<ROWBLOCKS, 512>>>(a, b, k);
        col_gemv<<<dim3(32, 9), 256>>>(k);
    }
    loss_kernel<<<1, 1024>>>(a, b, out);
}

// round 2
// speedup vs baseline: 3.1099x; 3.1099x over previous
#include <cuda_runtime.h>
#include <cuda_fp16.h>
#include <cuda_fp8.h>

#define NN 8192
#define EPSI 0.1f
#define NITERS 50

// K = exp(M/eps) stored as e5m2 fp8 (range [1, 22026.5] fits; decode = byte<<8 == fp16).
__device__ __align__(16) unsigned char dK8[(size_t)NN * NN];   // 64MB
__device__ float dU[NN];                          // true u = a/(K v)
__device__ float dColAcc[(NITERS + 1) * NN];      // colAcc[k] -> v_k = b/colAcc[k]
__device__ float dR[NN];                          // row sums of target
__device__ float dCs[NN];                         // col sums of target
__device__ float dDot;                            // sum(target * M)

__device__ __forceinline__ __half2 e5lo(unsigned int x) {
    unsigned int r = __byte_perm(x, 0u, 0x1404);   // bytes [0,b0,0,b1] -> half2{b0<<8, b1<<8}
    return *reinterpret_cast<__half2*>(&r);
}
__device__ __forceinline__ __half2 e5hi(unsigned int x) {
    unsigned int r = __byte_perm(x, 0u, 0x3424);   // bytes [0,b2,0,b3]
    return *reinterpret_cast<__half2*>(&r);
}
__device__ __forceinline__ __half2 u2h(unsigned int x) {
    return *reinterpret_cast<__half2*>(&x);
}

__global__ void init_kernel(const float* __restrict__ b) {
    int idx = blockIdx.x * blockDim.x + threadIdx.x;
    if (idx < (NITERS + 1) * NN) {
        int k = idx / NN, j = idx - k * NN;
        dColAcc[idx] = (k == 0) ? b[j] : 0.f;      // v_0 = b/b = 1
        if (k == 0) { dR[j] = 0.f; dCs[j] = 0.f; }
    }
    if (idx == 0) dDot = 0.f;
}

// One pass over M and target: build K (e5m2), row/col sums of target, dot(target, M).
// Grid (32 col-tiles of 256, 32 row-chunks of 256), 256 threads.
__global__ void __launch_bounds__(256) prep_kernel(const float* __restrict__ M,
                                                   const float* __restrict__ T) {
    __shared__ float sred[8 * 256];
    __shared__ float sdot[256];
    const int w = threadIdx.x >> 5, l = threadIdx.x & 31;
    const int col0 = blockIdx.x * 256 + l * 8;
    const int r0 = blockIdx.y * 256;
    const float SC = 10.0f * 1.4426950408889634f;   // (1/eps) * log2(e)

    float cs[8];
#pragma unroll
    for (int k = 0; k < 8; k++) cs[k] = 0.f;
    float dot = 0.f;

    for (int r = r0 + w; r < r0 + 256; r += 8) {
        size_t base = (size_t)r * NN + col0;
        float4 m0 = *reinterpret_cast<const float4*>(M + base);
        float4 m1 = *reinterpret_cast<const float4*>(M + base + 4);
        float4 t0 = *reinterpret_cast<const float4*>(T + base);
        float4 t1 = *reinterpret_cast<const float4*>(T + base + 4);

        union { uint2 u; __nv_fp8x2_storage_t s[4]; } P;
        P.s[0] = __nv_cvt_float2_to_fp8x2(make_float2(exp2f(m0.x * SC), exp2f(m0.y * SC)),
                                          __NV_SATFINITE, __NV_E5M2);
        P.s[1] = __nv_cvt_float2_to_fp8x2(make_float2(exp2f(m0.z * SC), exp2f(m0.w * SC)),
                                          __NV_SATFINITE, __NV_E5M2);
        P.s[2] = __nv_cvt_float2_to_fp8x2(make_float2(exp2f(m1.x * SC), exp2f(m1.y * SC)),
                                          __NV_SATFINITE, __NV_E5M2);
        P.s[3] = __nv_cvt_float2_to_fp8x2(make_float2(exp2f(m1.z * SC), exp2f(m1.w * SC)),
                                          __NV_SATFINITE, __NV_E5M2);
        *reinterpret_cast<uint2*>(dK8 + base) = P.u;

        cs[0] += t0.x; cs[1] += t0.y; cs[2] += t0.z; cs[3] += t0.w;
        cs[4] += t1.x; cs[5] += t1.y; cs[6] += t1.z; cs[7] += t1.w;

        dot += m0.x * t0.x + m0.y * t0.y + m0.z * t0.z + m0.w * t0.w
             + m1.x * t1.x + m1.y * t1.y + m1.z * t1.z + m1.w * t1.w;

        float rs = t0.x + t0.y + t0.z + t0.w + t1.x + t1.y + t1.z + t1.w;
#pragma unroll
        for (int o = 16; o > 0; o >>= 1) rs += __shfl_xor_sync(0xffffffffu, rs, o);
        if (l == 0) atomicAdd(&dR[r], rs);
    }

#pragma unroll
    for (int k = 0; k < 8; k++) sred[w * 256 + l * 8 + k] = cs[k];
    sdot[threadIdx.x] = dot;
    __syncthreads();

    float s = 0.f;
#pragma unroll
    for (int w2 = 0; w2 < 8; w2++) s += sred[w2 * 256 + threadIdx.x];
    atomicAdd(&dCs[blockIdx.x * 256 + threadIdx.x], s);

    for (int off = 128; off > 0; off >>= 1) {
        if (threadIdx.x < off) sdot[threadIdx.x] += sdot[threadIdx.x + off];
        __syncthreads();
    }
    if (threadIdx.x == 0) atomicAdd(&dDot, sdot[0]);
}

// u_i = a_i / sum_j K_ij v_j. v built in smem as half, pre-scaled by 2^-8 so half2
// accumulation chains (depth 16 per acc) stay in [~0.5, ~3000]. 512 blocks x 512 thr,
// warp per row, 16 rows per block.
__global__ void __launch_bounds__(512, 2) row_gemv(const float* __restrict__ a,
                                                   const float* __restrict__ b, int iter) {
    __shared__ __half svA[NN / 2];   // halfs 0..7 of each 16-elem chunk (de-interleaved)
    __shared__ __half svB[NN / 2];   // halfs 8..15
    const float* acc = dColAcc + (size_t)iter * NN;
    for (int j = threadIdx.x; j < NN; j += 512) {
        float v = __fdividef(b[j], acc[j]) * 0.00390625f;   // * 2^-8
        int c = j >> 4, p = j & 15;
        if (p < 8) svA[c * 8 + p] = __float2half(v);
        else       svB[c * 8 + (p - 8)] = __float2half(v);
    }
    __syncthreads();

    const int w = threadIdx.x >> 5, l = threadIdx.x & 31;
    const int r = blockIdx.x * 16 + w;
    const uint4* Kr = reinterpret_cast<const uint4*>(dK8 + (size_t)r * NN);
    const uint4* vA = reinterpret_cast<const uint4*>(svA);
    const uint4* vB = reinterpret_cast<const uint4*>(svB);

    __half2 s0, s1, s2, s3, s4, s5, s6, s7;
    s0 = s1 = s2 = s3 = s4 = s5 = s6 = s7 = __float2half2_rn(0.f);

#pragma unroll
    for (int it = 0; it < NN / (16 * 32); it++) {   // 16 iterations
        int idx = it * 32 + l;
        uint4 kq = Kr[idx];
        uint4 va = vA[idx];
        uint4 vb = vB[idx];
        s0 = __hfma2(e5lo(kq.x), u2h(va.x), s0);
        s1 = __hfma2(e5hi(kq.x), u2h(va.y), s1);
        s2 = __hfma2(e5lo(kq.y), u2h(va.z), s2);
        s3 = __hfma2(e5hi(kq.y), u2h(va.w), s3);
        s4 = __hfma2(e5lo(kq.z), u2h(vb.x), s4);
        s5 = __hfma2(e5hi(kq.z), u2h(vb.y), s5);
        s6 = __hfma2(e5lo(kq.w), u2h(vb.z), s6);
        s7 = __hfma2(e5hi(kq.w), u2h(vb.w), s7);
    }

    float2 f0 = __half22float2(s0), f1 = __half22float2(s1);
    float2 f2 = __half22float2(s2), f3 = __half22float2(s3);
    float2 f4 = __half22float2(s4), f5 = __half22float2(s5);
    float2 f6 = __half22float2(s6), f7 = __half22float2(s7);
    float sum = ((f0.x + f0.y) + (f1.x + f1.y)) + ((f2.x + f2.y) + (f3.x + f3.y))
              + ((f4.x + f4.y) + (f5.x + f5.y)) + ((f6.x + f6.y) + (f7.x + f7.y));
#pragma unroll
    for (int o = 16; o > 0; o >>= 1) sum += __shfl_xor_sync(0xffffffffu, sum, o);
    if (l == 0) dU[r] = (a[r] * 0.00390625f) / sum;   // a*2^-8 / (rowsum*2^-8)
}

// colAcc[iter+1][j] = sum_i K_ij u_i. u pre-scaled by 2^31 into half smem (u ~ 6.8e-12
// -> su ~ 0.015, products ~30, chains of 16 rows per acc). Grid (16 col-tiles of 512,
// 64 row-chunks of 128), 256 threads.
__global__ void __launch_bounds__(256) col_gemv(int iter) {
    __shared__ __half su[128];
    __shared__ float sred[8][512];
    const int r0 = blockIdx.y * 128;
    if (threadIdx.x < 128)
        su[threadIdx.x] = __float2half(dU[r0 + threadIdx.x] * 2147483648.0f);  // * 2^31
    __syncthreads();

    const int w = threadIdx.x >> 5, l = threadIdx.x & 31;
    const size_t col0 = (size_t)blockIdx.x * 512 + l * 16;

    __half2 s[8];
#pragma unroll
    for (int p = 0; p < 8; p++) s[p] = __float2half2_rn(0.f);

#pragma unroll 4
    for (int i = 0; i < 16; i++) {
        int rl = w + 8 * i;                        // local row 0..127
        uint4 kq = *reinterpret_cast<const uint4*>(dK8 + (size_t)(r0 + rl) * NN + col0);
        __half2 uu = __half2half2(su[rl]);
        s[0] = __hfma2(e5lo(kq.x), uu, s[0]);
        s[1] = __hfma2(e5hi(kq.x), uu, s[1]);
        s[2] = __hfma2(e5lo(kq.y), uu, s[2]);
        s[3] = __hfma2(e5hi(kq.y), uu, s[3]);
        s[4] = __hfma2(e5lo(kq.z), uu, s[4]);
        s[5] = __hfma2(e5hi(kq.z), uu, s[5]);
        s[6] = __hfma2(e5lo(kq.w), uu, s[6]);
        s[7] = __hfma2(e5hi(kq.w), uu, s[7]);
    }

#pragma unroll
    for (int p = 0; p < 8; p++) {
        float2 f = __half22float2(s[p]);
        sred[w][l * 16 + 2 * p]     = f.x;
        sred[w][l * 16 + 2 * p + 1] = f.y;
    }
    __syncthreads();

    for (int c = threadIdx.x; c < 512; c += 256) {
        float t = 0.f;
#pragma unroll
        for (int w2 = 0; w2 < 8; w2++) t += sred[w2][c];
        atomicAdd(&dColAcc[(size_t)(iter + 1) * NN + blockIdx.x * 512 + c],
                  t * (1.0f / 2147483648.0f));     // undo 2^31 u scale
    }
}

// loss = -( dot(target,M)/eps + sum_i R_i ln u_i + sum_j C_j ln v_j )
__global__ void loss_kernel(const float* __restrict__ a, const float* __restrict__ b,
                            float* __restrict__ out) {
    __shared__ float sred[1024];
    const float* accL = dColAcc + (size_t)NITERS * NN;
    float p = 0.f;
    for (int i = threadIdx.x; i < NN; i += 1024) {
        p += dR[i] * logf(dU[i]);
        p += dCs[i] * (logf(b[i]) - logf(accL[i]));
    }
    sred[threadIdx.x] = p;
    __syncthreads();
    for (int off = 512; off > 0; off >>= 1) {
        if (threadIdx.x < off) sred[threadIdx.x] += sred[threadIdx.x + off];
        __syncthreads();
    }
    if (threadIdx.x == 0) out[0] = -(sred[0] + dDot * (1.0f / EPSI));
}

extern "C" void kernel_launch(void* const* d_in, const int* in_sizes, int n_in,
                              void* d_out, int out_size) {
    const float* M = (const float*)d_in[0];
    const float* T = (const float*)d_in[1];
    const float* a = (const float*)d_in[2];
    const float* b = (const float*)d_in[3];
    float* out = (float*)d_out;

    init_kernel<<<((NITERS + 1) * NN + 255) / 256, 256>>>(b);
    prep_kernel<<<dim3(32, 32), 256>>>(M, T);
    for (int k = 0; k < NITERS; k++) {
        row_gemv<<<512, 512>>>(a, b, k);
        col_gemv<<<dim3(16, 64), 256>>>(k);
    }
    loss_kernel<<<1, 1024>>>(a, b, out);
}

// round 4
// speedup vs baseline: 3.2037x; 1.0302x over previous
#include <cuda_runtime.h>
#include <cuda_fp16.h>
#include <cuda_fp8.h>

#define NN 8192
#define EPSI 0.1f
#define NITERS 50

// K = exp(M/eps) stored as e5m2 fp8 (range [1, 22026.5] fits; decode = byte<<8 == fp16).
// 64MB — fits GB300's ~126MB L2; kept resident via L2 evict_last cache-hint policy.
__device__ __align__(16) unsigned char dK8[(size_t)NN * NN];   // 64MB
__device__ float dU[NN];                          // true u = a/(K v)
__device__ float dColAcc[(NITERS + 1) * NN];      // colAcc[k] -> v_k = b/colAcc[k]
__device__ float dR[NN];                          // row sums of target
__device__ float dCs[NN];                         // col sums of target
__device__ float dDot;                            // sum(target * M)

__device__ __forceinline__ __half2 e5lo(unsigned int x) {
    unsigned int r = __byte_perm(x, 0u, 0x1404);   // bytes [0,b0,0,b1] -> half2{b0<<8, b1<<8}
    return *reinterpret_cast<__half2*>(&r);
}
__device__ __forceinline__ __half2 e5hi(unsigned int x) {
    unsigned int r = __byte_perm(x, 0u, 0x3424);   // bytes [0,b2,0,b3]
    return *reinterpret_cast<__half2*>(&r);
}
__device__ __forceinline__ __half2 u2h(unsigned int x) {
    return *reinterpret_cast<__half2*>(&x);
}

// L2 policies: evict_last for the K-resident window, evict_first for streams.
__device__ __forceinline__ unsigned long long pol_last() {
    unsigned long long p;
    asm("createpolicy.fractional.L2::evict_last.b64 %0, 1.0;" : "=l"(p));
    return p;
}
__device__ __forceinline__ unsigned long long pol_first() {
    unsigned long long p;
    asm("createpolicy.fractional.L2::evict_first.b64 %0, 1.0;" : "=l"(p));
    return p;
}

// K loads: keep resident in L2.
__device__ __forceinline__ uint4 ldK(const unsigned char* p, unsigned long long pol) {
    uint4 v;
    asm volatile("ld.global.nc.L2::cache_hint.v4.u32 {%0,%1,%2,%3}, [%4], %5;"
                 : "=r"(v.x), "=r"(v.y), "=r"(v.z), "=r"(v.w) : "l"(p), "l"(pol));
    return v;
}
// K store from prep: seed the resident window.
__device__ __forceinline__ void stK(unsigned char* p, uint2 v, unsigned long long pol) {
    asm volatile("st.global.L2::cache_hint.v2.u32 [%0], {%1,%2}, %3;"
                 :: "l"(p), "r"(v.x), "r"(v.y), "l"(pol) : "memory");
}
// One-shot streaming loads (M, target): don't pollute the K window.
__device__ __forceinline__ float4 ldS(const float* p, unsigned long long pol) {
    float4 v;
    asm volatile("ld.global.nc.L2::cache_hint.v4.f32 {%0,%1,%2,%3}, [%4], %5;"
                 : "=f"(v.x), "=f"(v.y), "=f"(v.z), "=f"(v.w) : "l"(p), "l"(pol));
    return v;
}

__global__ void init_kernel(const float* __restrict__ b) {
    int idx = blockIdx.x * blockDim.x + threadIdx.x;
    if (idx < (NITERS + 1) * NN) {
        int k = idx / NN, j = idx - k * NN;
        dColAcc[idx] = (k == 0) ? b[j] : 0.f;      // v_0 = b/b = 1
        if (k == 0) { dR[j] = 0.f; dCs[j] = 0.f; }
    }
    if (idx == 0) dDot = 0.f;
}

// One pass over M and target: build K (e5m2), row/col sums of target, dot(target, M).
// Grid (32 col-tiles of 256, 32 row-chunks of 256), 256 threads.
__global__ void __launch_bounds__(256) prep_kernel(const float* __restrict__ M,
                                                   const float* __restrict__ T) {
    __shared__ float sred[8 * 256];
    __shared__ float sdot[256];
    const unsigned long long pF = pol_first();
    const unsigned long long pL = pol_last();
    const int w = threadIdx.x >> 5, l = threadIdx.x & 31;
    const int col0 = blockIdx.x * 256 + l * 8;
    const int r0 = blockIdx.y * 256;
    const float SC = 10.0f * 1.4426950408889634f;   // (1/eps) * log2(e)

    float cs[8];
#pragma unroll
    for (int k = 0; k < 8; k++) cs[k] = 0.f;
    float dot = 0.f;

    for (int r = r0 + w; r < r0 + 256; r += 8) {
        size_t base = (size_t)r * NN + col0;
        float4 m0 = ldS(M + base, pF);
        float4 m1 = ldS(M + base + 4, pF);
        float4 t0 = ldS(T + base, pF);
        float4 t1 = ldS(T + base + 4, pF);

        union { uint2 u; __nv_fp8x2_storage_t s[4]; } P;
        P.s[0] = __nv_cvt_float2_to_fp8x2(make_float2(exp2f(m0.x * SC), exp2f(m0.y * SC)),
                                          __NV_SATFINITE, __NV_E5M2);
        P.s[1] = __nv_cvt_float2_to_fp8x2(make_float2(exp2f(m0.z * SC), exp2f(m0.w * SC)),
                                          __NV_SATFINITE, __NV_E5M2);
        P.s[2] = __nv_cvt_float2_to_fp8x2(make_float2(exp2f(m1.x * SC), exp2f(m1.y * SC)),
                                          __NV_SATFINITE, __NV_E5M2);
        P.s[3] = __nv_cvt_float2_to_fp8x2(make_float2(exp2f(m1.z * SC), exp2f(m1.w * SC)),
                                          __NV_SATFINITE, __NV_E5M2);
        stK(dK8 + base, P.u, pL);

        cs[0] += t0.x; cs[1] += t0.y; cs[2] += t0.z; cs[3] += t0.w;
        cs[4] += t1.x; cs[5] += t1.y; cs[6] += t1.z; cs[7] += t1.w;

        dot += m0.x * t0.x + m0.y * t0.y + m0.z * t0.z + m0.w * t0.w
             + m1.x * t1.x + m1.y * t1.y + m1.z * t1.z + m1.w * t1.w;

        float rs = t0.x + t0.y + t0.z + t0.w + t1.x + t1.y + t1.z + t1.w;
#pragma unroll
        for (int o = 16; o > 0; o >>= 1) rs += __shfl_xor_sync(0xffffffffu, rs, o);
        if (l == 0) atomicAdd(&dR[r], rs);
    }

#pragma unroll
    for (int k = 0; k < 8; k++) sred[w * 256 + l * 8 + k] = cs[k];
    sdot[threadIdx.x] = dot;
    __syncthreads();

    float s = 0.f;
#pragma unroll
    for (int w2 = 0; w2 < 8; w2++) s += sred[w2 * 256 + threadIdx.x];
    atomicAdd(&dCs[blockIdx.x * 256 + threadIdx.x], s);

    for (int off = 128; off > 0; off >>= 1) {
        if (threadIdx.x < off) sdot[threadIdx.x] += sdot[threadIdx.x + off];
        __syncthreads();
    }
    if (threadIdx.x == 0) atomicAdd(&dDot, sdot[0]);
}

// u_i = a_i / sum_j K_ij v_j. v built in smem as half, pre-scaled by 2^-8 so half2
// accumulation chains (depth 16 per acc) stay in [~0.5, ~3000]. 512 blocks x 512 thr,
// warp per row, 16 rows per block.
__global__ void __launch_bounds__(512, 2) row_gemv(const float* __restrict__ a,
                                                   const float* __restrict__ b, int iter) {
    __shared__ __half svA[NN / 2];   // halfs 0..7 of each 16-elem chunk (de-interleaved)
    __shared__ __half svB[NN / 2];   // halfs 8..15
    const unsigned long long pL = pol_last();
    const float* acc = dColAcc + (size_t)iter * NN;
    for (int j = threadIdx.x; j < NN; j += 512) {
        float v = __fdividef(b[j], acc[j]) * 0.00390625f;   // * 2^-8
        int c = j >> 4, p = j & 15;
        if (p < 8) svA[c * 8 + p] = __float2half(v);
        else       svB[c * 8 + (p - 8)] = __float2half(v);
    }
    __syncthreads();

    const int w = threadIdx.x >> 5, l = threadIdx.x & 31;
    const int r = blockIdx.x * 16 + w;
    const unsigned char* Kr = dK8 + (size_t)r * NN;
    const uint4* vA = reinterpret_cast<const uint4*>(svA);
    const uint4* vB = reinterpret_cast<const uint4*>(svB);

    __half2 s0, s1, s2, s3, s4, s5, s6, s7;
    s0 = s1 = s2 = s3 = s4 = s5 = s6 = s7 = __float2half2_rn(0.f);

#pragma unroll
    for (int it = 0; it < NN / (16 * 32); it++) {   // 16 iterations
        int idx = it * 32 + l;
        uint4 kq = ldK(Kr + idx * 16, pL);
        uint4 va = vA[idx];
        uint4 vb = vB[idx];
        s0 = __hfma2(e5lo(kq.x), u2h(va.x), s0);
        s1 = __hfma2(e5hi(kq.x), u2h(va.y), s1);
        s2 = __hfma2(e5lo(kq.y), u2h(va.z), s2);
        s3 = __hfma2(e5hi(kq.y), u2h(va.w), s3);
        s4 = __hfma2(e5lo(kq.z), u2h(vb.x), s4);
        s5 = __hfma2(e5hi(kq.z), u2h(vb.y), s5);
        s6 = __hfma2(e5lo(kq.w), u2h(vb.z), s6);
        s7 = __hfma2(e5hi(kq.w), u2h(vb.w), s7);
    }

    float2 f0 = __half22float2(s0), f1 = __half22float2(s1);
    float2 f2 = __half22float2(s2), f3 = __half22float2(s3);
    float2 f4 = __half22float2(s4), f5 = __half22float2(s5);
    float2 f6 = __half22float2(s6), f7 = __half22float2(s7);
    float sum = ((f0.x + f0.y) + (f1.x + f1.y)) + ((f2.x + f2.y) + (f3.x + f3.y))
              + ((f4.x + f4.y) + (f5.x + f5.y)) + ((f6.x + f6.y) + (f7.x + f7.y));
#pragma unroll
    for (int o = 16; o > 0; o >>= 1) sum += __shfl_xor_sync(0xffffffffu, sum, o);
    if (l == 0) dU[r] = (a[r] * 0.00390625f) / sum;   // a*2^-8 / (rowsum*2^-8)
}

// colAcc[iter+1][j] = sum_i K_ij u_i. u pre-scaled by 2^31 into half smem (u ~ 6.8e-12
// -> su ~ 0.015, products ~30, chains of 16 rows per acc). Grid (16 col-tiles of 512,
// 64 row-chunks of 128), 256 threads.
__global__ void __launch_bounds__(256) col_gemv(int iter) {
    __shared__ __half su[128];
    __shared__ float sred[8][512];
    const unsigned long long pL = pol_last();
    const int r0 = blockIdx.y * 128;
    if (threadIdx.x < 128)
        su[threadIdx.x] = __float2half(dU[r0 + threadIdx.x] * 2147483648.0f);  // * 2^31
    __syncthreads();

    const int w = threadIdx.x >> 5, l = threadIdx.x & 31;
    const size_t col0 = (size_t)blockIdx.x * 512 + l * 16;

    __half2 s[8];
#pragma unroll
    for (int p = 0; p < 8; p++) s[p] = __float2half2_rn(0.f);

#pragma unroll 8
    for (int i = 0; i < 16; i++) {
        int rl = w + 8 * i;                        // local row 0..127
        uint4 kq = ldK(dK8 + (size_t)(r0 + rl) * NN + col0, pL);
        __half2 uu = __half2half2(su[rl]);
        s[0] = __hfma2(e5lo(kq.x), uu, s[0]);
        s[1] = __hfma2(e5hi(kq.x), uu, s[1]);
        s[2] = __hfma2(e5lo(kq.y), uu, s[2]);
        s[3] = __hfma2(e5hi(kq.y), uu, s[3]);
        s[4] = __hfma2(e5lo(kq.z), uu, s[4]);
        s[5] = __hfma2(e5hi(kq.z), uu, s[5]);
        s[6] = __hfma2(e5lo(kq.w), uu, s[6]);
        s[7] = __hfma2(e5hi(kq.w), uu, s[7]);
    }

#pragma unroll
    for (int p = 0; p < 8; p++) {
        float2 f = __half22float2(s[p]);
        sred[w][l * 16 + 2 * p]     = f.x;
        sred[w][l * 16 + 2 * p + 1] = f.y;
    }
    __syncthreads();

    for (int c = threadIdx.x; c < 512; c += 256) {
        float t = 0.f;
#pragma unroll
        for (int w2 = 0; w2 < 8; w2++) t += sred[w2][c];
        atomicAdd(&dColAcc[(size_t)(iter + 1) * NN + blockIdx.x * 512 + c],
                  t * (1.0f / 2147483648.0f));     // undo 2^31 u scale
    }
}

// loss = -( dot(target,M)/eps + sum_i R_i ln u_i + sum_j C_j ln v_j )
__global__ void loss_kernel(const float* __restrict__ a, const float* __restrict__ b,
                            float* __restrict__ out) {
    __shared__ float sred[1024];
    const float* accL = dColAcc + (size_t)NITERS * NN;
    float p = 0.f;
    for (int i = threadIdx.x; i < NN; i += 1024) {
        p += dR[i] * logf(dU[i]);
        p += dCs[i] * (logf(b[i]) - logf(accL[i]));
    }
    sred[threadIdx.x] = p;
    __syncthreads();
    for (int off = 512; off > 0; off >>= 1) {
        if (threadIdx.x < off) sred[threadIdx.x] += sred[threadIdx.x + off];
        __syncthreads();
    }
    if (threadIdx.x == 0) out[0] = -(sred[0] + dDot * (1.0f / EPSI));
}

extern "C" void kernel_launch(void* const* d_in, const int* in_sizes, int n_in,
                              void* d_out, int out_size) {
    const float* M = (const float*)d_in[0];
    const float* T = (const float*)d_in[1];
    const float* a = (const float*)d_in[2];
    const float* b = (const float*)d_in[3];
    float* out = (float*)d_out;

    init_kernel<<<((NITERS + 1) * NN + 255) / 256, 256>>>(b);
    prep_kernel<<<dim3(32, 32), 256>>>(M, T);
    for (int k = 0; k < NITERS; k++) {
        row_gemv<<<512, 512>>>(a, b, k);
        col_gemv<<<dim3(16, 64), 256>>>(k);
    }
    loss_kernel<<<1, 1024>>>(a, b, out);
}